// round 3
// baseline (speedup 1.0000x reference)
#include <cuda_runtime.h>
#include <math.h>

#define SAC_WARMUP 365
#define PF 4

__device__ __forceinline__ float fast_lg2(float x) {
    float r; asm("lg2.approx.f32 %0, %1;" : "=f"(r) : "f"(x)); return r;
}
__device__ __forceinline__ float fast_ex2(float x) {
    float r; asm("ex2.approx.f32 %0, %1;" : "=f"(r) : "f"(x)); return r;
}

struct Cst {
    float kc, pctim, adimp, uztwm, uzfwm, lztwm, lzfsm, lzfpm, pfree, riva;
    float rexp, uzk, lzsk, lzpk, ci, cgs, cgp;
    float r_uztwm, r_lztwm, r_ulz, r_lzfsm, r_lzfpm;
    float sfm, lzsum, r_lzsum, uzsum, parea, fp_frac, pbu, pbuz;
    float ci1, cgs1, cgp1, c1, c2, c3;
};

struct St {
    float auztw, alztw, uztw, uzfw, lztw, lzfs, lzfp;
    float qs, qi, qgs, qgp, o1;
};

__device__ __forceinline__ void load_consts(const float* __restrict__ params,
                                            int b, Cst& c)
{
    const float lo[21] = {0.1f, 0.0f, 0.0f, 10.0f, 10.0f, 50.0f, 10.0f, 50.0f,
                          0.0f, 0.0f, 0.0f, 5.0f, 1.0f, 0.1f, 0.01f, 0.001f,
                          0.5f, 0.95f, 0.98f, 0.0f, 0.0f};
    const float hi[21] = {1.2f, 0.1f, 0.3f, 100.0f, 100.0f, 400.0f, 100.0f, 1000.0f,
                          0.3f, 0.5f, 0.1f, 350.0f, 4.0f, 0.5f, 0.35f, 0.05f,
                          0.9f, 0.998f, 0.998f, 1.0f, 0.5f};
    float pr[21];
#pragma unroll
    for (int i = 0; i < 21; i++)
        pr[i] = lo[i] + params[(size_t)b * 21 + i] * (hi[i] - lo[i]);

    c.kc = pr[0];  c.pctim = pr[1];  c.adimp = pr[2];
    c.uztwm = pr[3]; c.uzfwm = pr[4]; c.lztwm = pr[5];
    c.lzfsm = pr[6]; c.lzfpm = pr[7];
    c.pfree = pr[9]; c.riva = pr[10];
    float zperc = pr[11];
    c.rexp = pr[12]; c.uzk = pr[13];
    c.lzsk = pr[14]; c.lzpk = pr[15];
    c.ci = pr[16]; c.cgs = pr[17]; c.cgp = pr[18];
    float ke = pr[19], xe = pr[20];

    c.r_uztwm = 1.0f / c.uztwm;
    c.r_lztwm = 1.0f / c.lztwm;
    c.r_ulz   = 1.0f / (c.uztwm + c.lztwm);
    c.r_lzfsm = 1.0f / c.lzfsm;
    c.r_lzfpm = 1.0f / c.lzfpm;
    c.sfm     = c.lzfsm + c.lzfpm;
    c.lzsum   = c.sfm + c.lztwm;
    c.r_lzsum = 1.0f / c.lzsum;
    c.uzsum   = c.uztwm + c.uzfwm;
    float pbase = c.lzfsm * c.lzsk + c.lzfpm * c.lzpk;
    c.parea   = 1.0f - c.pctim - c.adimp;
    c.fp_frac = c.lzfpm / c.sfm;
    c.pbu     = pbase / c.uzfwm;
    c.pbuz    = c.pbu * zperc;
    c.ci1     = (1.0f - c.ci)  * c.parea;
    c.cgs1    = (1.0f - c.cgs) * c.parea;
    c.cgp1    = (1.0f - c.cgp) * c.parea;
    const float dt = 0.5f;
    float mden = ke * (1.0f - xe) + dt;
    c.c1 = (ke * xe + dt) / mden;
    c.c2 = (dt - ke * xe) / mden;
    c.c3 = (ke * (1.0f - xe) - dt) / mden;
}

__device__ __forceinline__ void sac_step(const Cst& c, St& s,
                                         float pin, float ein,
                                         float& o2_out, float& et_out)
{
    float p = fmaxf(pin, 0.0f);
    float e = ein;
    if (!isfinite(e)) e = 0.0f;
    e = fmaxf(e, 0.0f);

    float ep    = c.kc * e;
    float roimp = c.pctim * p;
    float ae2   = c.pctim * ep;

    // ADIMP water balance
    float ae1    = fminf(s.auztw, ep * (s.auztw * c.r_uztwm));
    float ae3    = fmaxf((ep - ae1) * (s.alztw * c.r_ulz), 0.0f);
    float pav    = fmaxf(p - (c.uztwm - (s.auztw - ae1)), 0.0f);
    float almae3 = s.alztw - ae3;
    float adsur  = fmaxf(pav * (almae3 * c.r_lztwm), 0.0f);
    float ars    = fmaxf(pav - adsur + almae3 - c.lztwm, 0.0f);
    float auztw_n = fmaxf(fminf(c.uztwm, s.auztw - ae1 + p), 0.0f);
    float alztw_n = fmaxf(fminf(c.lztwm, pav - adsur + almae3), 0.0f);

    // pervious-area ET
    float e1  = fminf(s.uztw, ep * (s.uztw * c.r_uztwm));
    float e2  = fmaxf(fminf(s.uzfw, ep - e1), 0.0f);
    float e3  = fmaxf((ep - e1 - e2) * (s.lztw * c.r_ulz), 0.0f);
    float lt1 = fmaxf(s.lztw - e3, 0.0f);
    float e4  = c.riva * ep;
    float et  = ae2 + ae1 + ae3 + e1 + e2 + e3 + e4;

    // upper zone
    float uzres = p + (s.uztw + s.uzfw - e1 - e2);
    float rs = fmaxf(uzres - c.uzsum, 0.0f) * c.parea;
    float ut = fmaxf(fminf(c.uztwm, s.uztw - e1 + p), 0.0f);
    float uf = fmaxf(fminf(c.uzfwm, uzres - ut), 0.0f);
    float ri = uf * c.uzk;
    uf = fmaxf(uf - ri, 0.0f);

    // percolation; coef depends only on carry -> off critical path
    float coef = c.fp_frac * (2.0f * (1.0f - s.lzfp * c.r_lzfpm))
               / ((1.0f - s.lzfp * c.r_lzfpm) + (1.0f - s.lzfs * c.r_lzfsm));
    coef = fminf(coef, 1.0f);

    float lzdef = s.lzfs + s.lzfp + lt1;
    float defr  = fmaxf(1.0f - lzdef * c.r_lzsum, 0.0f);
    float pw    = fast_ex2(c.rexp * fast_lg2(defr));  // defr^rexp; 0^r -> 0
    float perc  = (c.pbu + c.pbuz * pw) * uf;
    float rate  = fmaxf(fminf(perc, c.lzsum - lzdef), 0.0f);
    uf = fmaxf(uf - rate, 0.0f);

    float fx    = fmaxf(fminf(c.sfm - (s.lzfs + s.lzfp),
                              fmaxf(rate - (c.lztwm - lt1), rate * c.pfree)), 0.0f);
    float perct = rate - fx;
    float percp = fmaxf(fminf(c.lzfpm - s.lzfp,
                              fmaxf(fx - (c.lzfsm - s.lzfs), coef * fx)), 0.0f);
    float percs = fmaxf(fx - percp, 0.0f);

    float lt = fminf(lt1 + perct, c.lztwm);
    float ls = s.lzfs + percs;
    float lp = s.lzfp + percp;
    float rgs = ls * c.lzsk;  ls = fmaxf(ls - rgs, 0.0f);
    float rgp = lp * c.lzpk;  lp = fmaxf(lp - rgp, 0.0f);

    // routing
    float i1   = s.qs + s.qi + s.qgs + s.qgp;
    float qs_n = roimp + adsur * c.adimp + ars * c.adimp + rs;
    float qi_n = c.ci  * s.qi  + c.ci1  * ri;
    float qgs_n = c.cgs * s.qgs + c.cgs1 * rgs;
    float qgp_n = c.cgp * s.qgp + c.cgp1 * rgp;
    float i2   = qs_n + qi_n + qgs_n + qgp_n;
    float o2   = c.c1 * i1 + c.c2 * i2 + c.c3 * s.o1;

    s.auztw = auztw_n; s.alztw = alztw_n;
    s.uztw = ut; s.uzfw = uf; s.lztw = lt; s.lzfs = ls; s.lzfp = lp;
    s.qs = qs_n; s.qi = qi_n; s.qgs = qgs_n; s.qgp = qgp_n;
    s.o1 = o2;

    o2_out = o2;
    et_out = et;
}

// 2 basins per thread: independent recurrence chains interleaved for ILP.
__global__ __launch_bounds__(32, 1)
void sac4dpl_kernel2(const float* __restrict__ p_and_e,   // [T, B, 2]
                     const float* __restrict__ params,    // [B, 21]
                     float* __restrict__ out,             // [2, T-WARMUP, B]
                     int T, int B)
{
    int tb = blockIdx.x * 32 + threadIdx.x;   // pair index
    int B2 = B >> 1;
    if (tb >= B2) return;
    int b0 = tb * 2;

    Cst c0, c1;
    load_consts(params, b0,     c0);
    load_consts(params, b0 + 1, c1);

    St s0, s1;
    s0.auztw = s0.alztw = s0.uztw = s0.uzfw = s0.lztw = s0.lzfs = s0.lzfp = 0.01f;
    s0.qs = s0.qi = s0.qgs = s0.qgp = s0.o1 = 0.01f;
    s1 = s0;

    // input as float4: (p0, e0, p1, e1) for basin pair at row t
    const float4* __restrict__ pe4 = (const float4*)p_and_e;
    const int nout = T - SAC_WARMUP;
    float2* __restrict__ qout = (float2*)out;                        // [nout, B2] of float2
    float2* __restrict__ eout = (float2*)(out + (size_t)nout * B);

    float4 buf[PF];
#pragma unroll
    for (int i = 0; i < PF; i++)
        buf[i] = pe4[(size_t)i * B2 + tb];

    float o2a, eta, o2b, etb;

    // ---- warmup: no stores ----
#pragma unroll 2
    for (int t = 0; t < SAC_WARMUP; ++t) {
        float4 cur = buf[t & (PF - 1)];
        buf[t & (PF - 1)] = pe4[(size_t)(t + PF) * B2 + tb];
        sac_step(c0, s0, cur.x, cur.y, o2a, eta);
        sac_step(c1, s1, cur.z, cur.w, o2b, etb);
    }

    // ---- output phase ----
#pragma unroll 2
    for (int t = SAC_WARMUP; t < T; ++t) {
        float4 cur = buf[t & (PF - 1)];
        int tp = t + PF;
        if (tp < T)
            buf[t & (PF - 1)] = pe4[(size_t)tp * B2 + tb];

        sac_step(c0, s0, cur.x, cur.y, o2a, eta);
        sac_step(c1, s1, cur.z, cur.w, o2b, etb);

        size_t o = (size_t)(t - SAC_WARMUP) * B2 + tb;
        qout[o] = make_float2(o2a, o2b);
        eout[o] = make_float2(eta, etb);
    }
}

extern "C" void kernel_launch(void* const* d_in, const int* in_sizes, int n_in,
                              void* d_out, int out_size)
{
    const float* p_and_e = (const float*)d_in[0];   // [T, B, 2]
    const float* params  = (const float*)d_in[1];   // [B, 21]
    float* out = (float*)d_out;

    int B = in_sizes[1] / 21;
    int T = in_sizes[0] / (2 * B);

    int B2 = B / 2;
    int grid = (B2 + 31) / 32;
    sac4dpl_kernel2<<<grid, 32>>>(p_and_e, params, out, T, B);
}

// round 4
// speedup vs baseline: 1.3939x; 1.3939x over previous
#include <cuda_runtime.h>
#include <math.h>

#define SAC_WARMUP 365
#define PF 4

// ---- 2-lane scalar pair: both basins advance in adjacent independent ops ----
struct f2 { float a, b; };
__device__ __forceinline__ f2 F2(float v) { f2 r; r.a = v; r.b = v; return r; }
__device__ __forceinline__ f2 operator+(f2 u, f2 v) { f2 r; r.a = u.a + v.a; r.b = u.b + v.b; return r; }
__device__ __forceinline__ f2 operator-(f2 u, f2 v) { f2 r; r.a = u.a - v.a; r.b = u.b - v.b; return r; }
__device__ __forceinline__ f2 operator*(f2 u, f2 v) { f2 r; r.a = u.a * v.a; r.b = u.b * v.b; return r; }
__device__ __forceinline__ f2 fmax2(f2 u, f2 v) { f2 r; r.a = fmaxf(u.a, v.a); r.b = fmaxf(u.b, v.b); return r; }
__device__ __forceinline__ f2 fmin2(f2 u, f2 v) { f2 r; r.a = fminf(u.a, v.a); r.b = fminf(u.b, v.b); return r; }
__device__ __forceinline__ f2 fdiv2(f2 u, f2 v) { f2 r; r.a = u.a / v.a; r.b = u.b / v.b; return r; }
// x^r via MUFU lg2/ex2; lg2(0) = -inf -> ex2(-inf) = 0, matching jnp.power(0, r>=1) = 0
__device__ __forceinline__ f2 powr2(f2 x, f2 r) {
    float la, lb, ea, eb;
    asm("lg2.approx.f32 %0, %1;" : "=f"(la) : "f"(x.a));
    asm("lg2.approx.f32 %0, %1;" : "=f"(lb) : "f"(x.b));
    la *= r.a; lb *= r.b;
    asm("ex2.approx.f32 %0, %1;" : "=f"(ea) : "f"(la));
    asm("ex2.approx.f32 %0, %1;" : "=f"(eb) : "f"(lb));
    f2 o; o.a = ea; o.b = eb; return o;
}

struct Cst {
    f2 kc, pctim, adimp, uztwm, lztwm, lzfsm, lzfpm, pfree, riva;
    f2 rexp, uzk, lzsk, lzpk, ci, cgs, cgp;
    f2 r_uztwm, r_lztwm, r_ulz, r_lzfsm, r_lzfpm;
    f2 sfm, lzsum, uzfwm, r_lzsum, uzsum, parea, fp_frac, pbu, pbuz;
    f2 ci1, cgs1, cgp1, c1, c2, c3;
};

struct St {
    f2 auztw, alztw, uztw, uzfw, lztw, lzfs, lzfp;
    f2 qs, qi, qgs, qgp, o1;
};

__device__ __forceinline__ void load_lane(const float* __restrict__ params,
                                          int b, int lane, Cst& c)
{
    const float lo[21] = {0.1f, 0.0f, 0.0f, 10.0f, 10.0f, 50.0f, 10.0f, 50.0f,
                          0.0f, 0.0f, 0.0f, 5.0f, 1.0f, 0.1f, 0.01f, 0.001f,
                          0.5f, 0.95f, 0.98f, 0.0f, 0.0f};
    const float hi[21] = {1.2f, 0.1f, 0.3f, 100.0f, 100.0f, 400.0f, 100.0f, 1000.0f,
                          0.3f, 0.5f, 0.1f, 350.0f, 4.0f, 0.5f, 0.35f, 0.05f,
                          0.9f, 0.998f, 0.998f, 1.0f, 0.5f};
    float pr[21];
#pragma unroll
    for (int i = 0; i < 21; i++)
        pr[i] = lo[i] + params[(size_t)b * 21 + i] * (hi[i] - lo[i]);

    float kc = pr[0], pctim = pr[1], adimp = pr[2];
    float uztwm = pr[3], uzfwm = pr[4], lztwm = pr[5];
    float lzfsm = pr[6], lzfpm = pr[7];
    float pfree = pr[9], riva = pr[10];
    float zperc = pr[11], rexp = pr[12], uzk = pr[13];
    float lzsk = pr[14], lzpk = pr[15];
    float ci = pr[16], cgs = pr[17], cgp = pr[18];
    float ke = pr[19], xe = pr[20];

    float sfm   = lzfsm + lzfpm;
    float lzsum = sfm + lztwm;
    float pbase = lzfsm * lzsk + lzfpm * lzpk;
    float parea = 1.0f - pctim - adimp;
    float pbu   = pbase / uzfwm;
    const float dt = 0.5f;
    float mden = ke * (1.0f - xe) + dt;

    float* dst = lane ? &c.kc.b : &c.kc.a;
    // fill lane via pointer stride-2 writes (struct is f2-array-like)
    // safer: explicit assignments
    (void)dst;
#define SET(field, val) do { if (lane) c.field.b = (val); else c.field.a = (val); } while (0)
    SET(kc, kc); SET(pctim, pctim); SET(adimp, adimp);
    SET(uztwm, uztwm); SET(lztwm, lztwm);
    SET(lzfsm, lzfsm); SET(lzfpm, lzfpm);
    SET(pfree, pfree); SET(riva, riva);
    SET(rexp, rexp); SET(uzk, uzk);
    SET(lzsk, lzsk); SET(lzpk, lzpk);
    SET(ci, ci); SET(cgs, cgs); SET(cgp, cgp);
    SET(r_uztwm, 1.0f / uztwm);
    SET(r_lztwm, 1.0f / lztwm);
    SET(r_ulz,   1.0f / (uztwm + lztwm));
    SET(r_lzfsm, 1.0f / lzfsm);
    SET(r_lzfpm, 1.0f / lzfpm);
    SET(sfm, sfm); SET(lzsum, lzsum); SET(uzfwm, uzfwm);
    SET(r_lzsum, 1.0f / lzsum);
    SET(uzsum, uztwm + uzfwm);
    SET(parea, parea);
    SET(fp_frac, lzfpm / sfm);
    SET(pbu, pbu);
    SET(pbuz, pbu * zperc);
    SET(ci1,  (1.0f - ci)  * parea);
    SET(cgs1, (1.0f - cgs) * parea);
    SET(cgp1, (1.0f - cgp) * parea);
    SET(c1, (ke * xe + dt) / mden);
    SET(c2, (dt - ke * xe) / mden);
    SET(c3, (ke * (1.0f - xe) - dt) / mden);
#undef SET
}

// one time step, BOTH basins advanced lane-parallel
__device__ __forceinline__ void sac_step2(const Cst& c, St& s,
                                          f2 pin, f2 ein,
                                          f2& o2_out, f2& et_out)
{
    const f2 Z = F2(0.0f);

    f2 p = fmax2(pin, Z);
    f2 e;
    e.a = isfinite(ein.a) ? fmaxf(ein.a, 0.0f) : 0.0f;
    e.b = isfinite(ein.b) ? fmaxf(ein.b, 0.0f) : 0.0f;

    f2 ep    = c.kc * e;
    f2 roimp = c.pctim * p;
    f2 ae2   = c.pctim * ep;

    // ADIMP water balance
    f2 ae1    = fmin2(s.auztw, ep * (s.auztw * c.r_uztwm));
    f2 ae3    = fmax2((ep - ae1) * (s.alztw * c.r_ulz), Z);
    f2 pav    = fmax2(p - (c.uztwm - (s.auztw - ae1)), Z);
    f2 almae3 = s.alztw - ae3;
    f2 adsur  = fmax2(pav * (almae3 * c.r_lztwm), Z);
    f2 ars    = fmax2(pav - adsur + almae3 - c.lztwm, Z);
    f2 auztw_n = fmax2(fmin2(c.uztwm, s.auztw - ae1 + p), Z);
    f2 alztw_n = fmax2(fmin2(c.lztwm, pav - adsur + almae3), Z);

    // pervious-area ET
    f2 e1  = fmin2(s.uztw, ep * (s.uztw * c.r_uztwm));
    f2 e2  = fmax2(fmin2(s.uzfw, ep - e1), Z);
    f2 e3  = fmax2((ep - e1 - e2) * (s.lztw * c.r_ulz), Z);
    f2 lt1 = fmax2(s.lztw - e3, Z);
    f2 e4  = c.riva * ep;
    f2 et  = ae2 + ae1 + ae3 + e1 + e2 + e3 + e4;

    // upper zone
    f2 uzres = p + (s.uztw + s.uzfw - e1 - e2);
    f2 rs = fmax2(uzres - c.uzsum, Z) * c.parea;
    f2 ut = fmax2(fmin2(c.uztwm, s.uztw - e1 + p), Z);
    f2 uf = fmax2(fmin2(c.uzfwm, uzres - ut), Z);
    f2 ri = uf * c.uzk;
    uf = fmax2(uf - ri, Z);

    // percolation; coef only depends on carry -> off critical path
    f2 one = F2(1.0f);
    f2 gp  = one - s.lzfp * c.r_lzfpm;
    f2 gs  = one - s.lzfs * c.r_lzfsm;
    f2 coef = fmin2(fdiv2(c.fp_frac * (F2(2.0f) * gp), gp + gs), one);

    f2 lzdef = s.lzfs + s.lzfp + lt1;
    f2 defr  = fmax2(one - lzdef * c.r_lzsum, Z);
    f2 pw    = powr2(defr, c.rexp);
    f2 perc  = (c.pbu + c.pbuz * pw) * uf;
    f2 rate  = fmax2(fmin2(perc, c.lzsum - lzdef), Z);
    uf = fmax2(uf - rate, Z);

    f2 fx    = fmax2(fmin2(c.sfm - (s.lzfs + s.lzfp),
                           fmax2(rate - (c.lztwm - lt1), rate * c.pfree)), Z);
    f2 perct = rate - fx;
    f2 percp = fmax2(fmin2(c.lzfpm - s.lzfp,
                           fmax2(fx - (c.lzfsm - s.lzfs), coef * fx)), Z);
    f2 percs = fmax2(fx - percp, Z);

    f2 lt = fmin2(lt1 + perct, c.lztwm);
    f2 ls = s.lzfs + percs;
    f2 lp = s.lzfp + percp;
    f2 rgs = ls * c.lzsk;  ls = fmax2(ls - rgs, Z);
    f2 rgp = lp * c.lzpk;  lp = fmax2(lp - rgp, Z);

    // routing
    f2 i1   = s.qs + s.qi + s.qgs + s.qgp;
    f2 qs_n = roimp + adsur * c.adimp + ars * c.adimp + rs;
    f2 qi_n = c.ci  * s.qi  + c.ci1  * ri;
    f2 qgs_n = c.cgs * s.qgs + c.cgs1 * rgs;
    f2 qgp_n = c.cgp * s.qgp + c.cgp1 * rgp;
    f2 i2   = qs_n + qi_n + qgs_n + qgp_n;
    f2 o2   = c.c1 * i1 + c.c2 * i2 + c.c3 * s.o1;

    s.auztw = auztw_n; s.alztw = alztw_n;
    s.uztw = ut; s.uzfw = uf; s.lztw = lt; s.lzfs = ls; s.lzfp = lp;
    s.qs = qs_n; s.qi = qi_n; s.qgs = qgs_n; s.qgp = qgp_n;
    s.o1 = o2;

    o2_out = o2;
    et_out = et;
}

__global__ __launch_bounds__(32, 1)
void sac4dpl_kernel2(const float* __restrict__ p_and_e,   // [T, B, 2]
                     const float* __restrict__ params,    // [B, 21]
                     float* __restrict__ out,             // [2, T-WARMUP, B]
                     int T, int B)
{
    int tb = blockIdx.x * 32 + threadIdx.x;   // basin-pair index
    int B2 = B >> 1;
    if (tb >= B2) return;

    Cst c;
    load_lane(params, tb * 2,     0, c);
    load_lane(params, tb * 2 + 1, 1, c);

    St s;
    s.auztw = s.alztw = s.uztw = s.uzfw = s.lztw = s.lzfs = s.lzfp = F2(0.01f);
    s.qs = s.qi = s.qgs = s.qgp = s.o1 = F2(0.01f);

    const float4* __restrict__ pe4 = (const float4*)p_and_e;  // (p0,e0,p1,e1)
    const int nout = T - SAC_WARMUP;
    float2* __restrict__ qout = (float2*)out;
    float2* __restrict__ eout = (float2*)(out + (size_t)nout * B);

    float4 buf[PF];
#pragma unroll
    for (int i = 0; i < PF; i++)
        buf[i] = pe4[(size_t)i * B2 + tb];

    f2 o2, et, pin, ein;

    // ---- warmup: no stores ----
    for (int t = 0; t < SAC_WARMUP; ++t) {
        float4 cur = buf[t & (PF - 1)];
        buf[t & (PF - 1)] = pe4[(size_t)(t + PF) * B2 + tb];
        pin.a = cur.x; ein.a = cur.y;
        pin.b = cur.z; ein.b = cur.w;
        sac_step2(c, s, pin, ein, o2, et);
    }

    // ---- output phase ----
    for (int t = SAC_WARMUP; t < T; ++t) {
        float4 cur = buf[t & (PF - 1)];
        int tp = t + PF;
        if (tp < T)
            buf[t & (PF - 1)] = pe4[(size_t)tp * B2 + tb];

        pin.a = cur.x; ein.a = cur.y;
        pin.b = cur.z; ein.b = cur.w;
        sac_step2(c, s, pin, ein, o2, et);

        size_t o = (size_t)(t - SAC_WARMUP) * B2 + tb;
        qout[o] = make_float2(o2.a, o2.b);
        eout[o] = make_float2(et.a, et.b);
    }
}

extern "C" void kernel_launch(void* const* d_in, const int* in_sizes, int n_in,
                              void* d_out, int out_size)
{
    const float* p_and_e = (const float*)d_in[0];   // [T, B, 2]
    const float* params  = (const float*)d_in[1];   // [B, 21]
    float* out = (float*)d_out;

    int B = in_sizes[1] / 21;
    int T = in_sizes[0] / (2 * B);

    int B2 = B / 2;
    int grid = (B2 + 31) / 32;
    sac4dpl_kernel2<<<grid, 32>>>(p_and_e, params, out, T, B);
}

// round 5
// speedup vs baseline: 4.3046x; 3.0883x over previous
#include <cuda_runtime.h>
#include <math.h>

#define SAC_WARMUP 365
#define PF 4

__device__ __forceinline__ float fast_lg2(float x) {
    float r; asm("lg2.approx.f32 %0, %1;" : "=f"(r) : "f"(x)); return r;
}
__device__ __forceinline__ float fast_ex2(float x) {
    float r; asm("ex2.approx.f32 %0, %1;" : "=f"(r) : "f"(x)); return r;
}
// rcp.approx + 1 Newton-Raphson step: ~full fp32 precision, 4 instrs, no slow-path
__device__ __forceinline__ float fast_rcp(float d) {
    float r; asm("rcp.approx.f32 %0, %1;" : "=f"(r) : "f"(d));
    r = r * (2.0f - d * r);
    return r;
}

__global__ __launch_bounds__(128, 1)
void sac4dpl_kernel(const float* __restrict__ p_and_e,   // [T, B, 2]
                    const float* __restrict__ params,    // [B, 21]
                    float* __restrict__ out,             // [2, T-WARMUP, B]
                    int T, int B)
{
    int b = blockIdx.x * 128 + threadIdx.x;
    if (b >= B) return;

    // ---- load + scale parameters (one-time) ----
    const float lo[21] = {0.1f, 0.0f, 0.0f, 10.0f, 10.0f, 50.0f, 10.0f, 50.0f,
                          0.0f, 0.0f, 0.0f, 5.0f, 1.0f, 0.1f, 0.01f, 0.001f,
                          0.5f, 0.95f, 0.98f, 0.0f, 0.0f};
    const float hi[21] = {1.2f, 0.1f, 0.3f, 100.0f, 100.0f, 400.0f, 100.0f, 1000.0f,
                          0.3f, 0.5f, 0.1f, 350.0f, 4.0f, 0.5f, 0.35f, 0.05f,
                          0.9f, 0.998f, 0.998f, 1.0f, 0.5f};
    float pr[21];
#pragma unroll
    for (int i = 0; i < 21; i++)
        pr[i] = lo[i] + params[(size_t)b * 21 + i] * (hi[i] - lo[i]);

    const float kc    = pr[0],  pctim = pr[1],  adimp = pr[2];
    const float uztwm = pr[3],  uzfwm = pr[4],  lztwm = pr[5];
    const float lzfsm = pr[6],  lzfpm = pr[7];
    const float pfree = pr[9],  riva  = pr[10];
    const float zperc = pr[11], rexp  = pr[12], uzk = pr[13];
    const float lzsk  = pr[14], lzpk  = pr[15];
    const float ci    = pr[16], cgs   = pr[17], cgp = pr[18];
    const float ke    = pr[19], xe    = pr[20];

    // ---- hoisted per-basin constants ----
    const float r_uztwm = 1.0f / uztwm;
    const float r_lztwm = 1.0f / lztwm;
    const float r_ulz   = 1.0f / (uztwm + lztwm);
    const float r_lzfsm = 1.0f / lzfsm;
    const float r_lzfpm = 1.0f / lzfpm;
    const float sfm     = lzfsm + lzfpm;
    const float lzsum   = sfm + lztwm;
    const float r_lzsum = 1.0f / lzsum;
    const float uzsum   = uztwm + uzfwm;
    const float pbase   = lzfsm * lzsk + lzfpm * lzpk;
    const float parea   = 1.0f - pctim - adimp;
    const float fp2     = 2.0f * (lzfpm / sfm);       // folded: fp_frac * 2
    const float pbu     = pbase / uzfwm;
    const float pbuz    = pbu * zperc;
    const float ci1     = (1.0f - ci)  * parea;
    const float cgs1    = (1.0f - cgs) * parea;
    const float cgp1    = (1.0f - cgp) * parea;
    const float dt      = 0.5f;
    const float mden    = ke * (1.0f - xe) + dt;
    const float c1      = (ke * xe + dt) / mden;
    const float c2      = (dt - ke * xe) / mden;
    const float c3      = (ke * (1.0f - xe) - dt) / mden;

    // ---- initial carry ----
    float auztw = 0.01f, alztw = 0.01f;
    float uztw  = 0.01f, uzfw  = 0.01f;
    float lztw  = 0.01f, lzfs  = 0.01f, lzfp = 0.01f;
    float qs = 0.01f, qi = 0.01f, qgs = 0.01f, qgp = 0.01f;
    float o1 = 0.01f;

    // pointer-increment addressing (no per-iter wide index math)
    const float2* __restrict__ pe  = (const float2*)p_and_e + b;   // advance by B per step
    const int nout = T - SAC_WARMUP;
    float* __restrict__ qout = out + b;                             // advance by B per step
    float* __restrict__ eout = out + (size_t)nout * B + b;

    // 4-deep prefetch ring (static register indexing via unroll 4)
    float2 buf[PF];
#pragma unroll
    for (int i = 0; i < PF; i++)
        buf[i] = pe[(size_t)i * B];
    const float2* __restrict__ pe_pf = pe + (size_t)PF * B;         // next prefetch addr

#pragma unroll 4
    for (int t = 0; t < T; ++t) {
        float2 cur = buf[t & (PF - 1)];
        if (t + PF < T) {
            buf[t & (PF - 1)] = *pe_pf;
        }
        pe_pf += B;

        float p = fmaxf(cur.x, 0.0f);
        float e = fmaxf(cur.y, 0.0f);     // inputs are finite by construction

        float ep    = kc * e;
        float roimp = pctim * p;
        float ae2   = pctim * ep;

        // ADIMP water balance
        float ae1    = fminf(auztw, ep * (auztw * r_uztwm));
        float ae3    = fmaxf((ep - ae1) * (alztw * r_ulz), 0.0f);
        float pav    = fmaxf(p - (uztwm - (auztw - ae1)), 0.0f);
        float almae3 = alztw - ae3;
        float adsur  = fmaxf(pav * (almae3 * r_lztwm), 0.0f);
        float ars    = fmaxf(pav - adsur + almae3 - lztwm, 0.0f);
        float auztw_n = fmaxf(fminf(uztwm, auztw - ae1 + p), 0.0f);
        float alztw_n = fmaxf(fminf(lztwm, pav - adsur + almae3), 0.0f);

        // pervious-area ET
        float e1  = fminf(uztw, ep * (uztw * r_uztwm));
        float e2  = fmaxf(fminf(uzfw, ep - e1), 0.0f);
        float e3  = fmaxf((ep - e1 - e2) * (lztw * r_ulz), 0.0f);
        float lt1 = fmaxf(lztw - e3, 0.0f);
        float e4  = riva * ep;
        float et  = ae2 + ae1 + ae3 + e1 + e2 + e3 + e4;

        // upper zone
        float uzres = p + (uztw + uzfw - e1 - e2);
        float rs = fmaxf(uzres - uzsum, 0.0f) * parea;
        float ut = fmaxf(fminf(uztwm, uztw - e1 + p), 0.0f);
        float uf = fmaxf(fminf(uzfwm, uzres - ut), 0.0f);
        float ri = uf * uzk;
        uf = fmaxf(uf - ri, 0.0f);

        // percolation; coef depends only on carry -> off critical path
        float gp = 1.0f - lzfp * r_lzfpm;
        float gs = 1.0f - lzfs * r_lzfsm;
        float coef = fminf(fp2 * gp * fast_rcp(gp + gs), 1.0f);

        float lzdef = lzfs + lzfp + lt1;
        float defr  = fmaxf(1.0f - lzdef * r_lzsum, 0.0f);
        float pw    = fast_ex2(rexp * fast_lg2(defr));  // defr^rexp; 0^r -> 0
        float perc  = (pbu + pbuz * pw) * uf;
        float rate  = fmaxf(fminf(perc, lzsum - lzdef), 0.0f);
        uf = fmaxf(uf - rate, 0.0f);

        float fx    = fmaxf(fminf(sfm - (lzfs + lzfp),
                                  fmaxf(rate - (lztwm - lt1), rate * pfree)), 0.0f);
        float perct = rate - fx;
        float percp = fmaxf(fminf(lzfpm - lzfp,
                                  fmaxf(fx - (lzfsm - lzfs), coef * fx)), 0.0f);
        float percs = fmaxf(fx - percp, 0.0f);

        float lt = fminf(lt1 + perct, lztwm);
        float ls = lzfs + percs;
        float lp = lzfp + percp;
        float rgs = ls * lzsk;  ls = fmaxf(ls - rgs, 0.0f);
        float rgp = lp * lzpk;  lp = fmaxf(lp - rgp, 0.0f);

        // routing
        float i1   = qs + qi + qgs + qgp;
        float qs_n = roimp + adsur * adimp + ars * adimp + rs;
        float qi_n = ci  * qi  + ci1  * ri;
        float qgs_n = cgs * qgs + cgs1 * rgs;
        float qgp_n = cgp * qgp + cgp1 * rgp;
        float i2   = qs_n + qi_n + qgs_n + qgp_n;
        float o2   = c1 * i1 + c2 * i2 + c3 * o1;

        if (t >= SAC_WARMUP) {
            *qout = o2;  qout += B;
            *eout = et;  eout += B;
        }

        // commit carry
        auztw = auztw_n; alztw = alztw_n;
        uztw = ut; uzfw = uf; lztw = lt; lzfs = ls; lzfp = lp;
        qs = qs_n; qi = qi_n; qgs = qgs_n; qgp = qgp_n;
        o1 = o2;
    }
}

extern "C" void kernel_launch(void* const* d_in, const int* in_sizes, int n_in,
                              void* d_out, int out_size)
{
    const float* p_and_e = (const float*)d_in[0];   // [T, B, 2]
    const float* params  = (const float*)d_in[1];   // [B, 21]
    float* out = (float*)d_out;

    int B = in_sizes[1] / 21;
    int T = in_sizes[0] / (2 * B);

    int grid = (B + 127) / 128;   // 79 blocks for B=10000 -> <=1 block/SM, 1 warp/SMSP
    sac4dpl_kernel<<<grid, 128>>>(p_and_e, params, out, T, B);
}